// round 7
// baseline (speedup 1.0000x reference)
#include <cuda_runtime.h>
#include <math.h>

// PPCA gating layer, GB300 sm_103a — round 7: 8 channels/thread, 75% occ.
// x: [B=64, C=256, H=56, W=56] fp32, weight: [HW=3136, 15] fp32.
//
// Calibration so far (traffic pinned at floor by reg/smem staging):
//   18 warps/SM -> 69% DRAM, 29 warps -> 74%. Rate is monotone in warps.
// This round: each thread owns 8 channels (4 float4 reg + 4 float4 smem),
// CTA = 512 thr = 16 lanes x 32 subgroups -> ~40 regs -> 3 CTAs/SM,
// 48 warps (75% occ).
//
// Gate thread folds 32 subgroup sums (8ch each) -> 8 group sums -> 15 feats,
// normalize (ddof=0), dot weight, sigmoid. Pass 2 multiplies staged data.

#define BATCH   64
#define CH      256
#define HW      3136
#define HW4     (HW / 4)      // 784 float4 per (b,c) row
#define TILE_S  64
#define LANES   (TILE_S / 4)  // 16 float4 lanes
#define NSUB    32            // channel subgroups (8 channels each)
#define NTHR    512           // 16 lanes x 32 subgroups
#define NREG    4             // channels kept in registers
#define NSMEM   4             // channels parked in smem

__global__ __launch_bounds__(NTHR, 3)
void ppca_gate_kernel(const float* __restrict__ x,
                      const float* __restrict__ weight,
                      float* __restrict__ out)
{
    __shared__ float4 sstage[NSMEM * NTHR];   // 32 KB staging
    __shared__ float  sgrp[NSUB * TILE_S];    // subgroup sums [32][64] = 8 KB
    __shared__ float  sgate[TILE_S];          // gates

    const int s0 = blockIdx.x * TILE_S;       // 49 tiles * 64 = 3136
    const int b  = blockIdx.y;

    const int t   = threadIdx.x;
    const int sl4 = t & (LANES - 1);          // float4 lane 0..15
    const int h   = t >> 4;                   // subgroup 0..31 (8 ch each)

    const size_t base4 = (size_t)b * CH * HW4 + (size_t)(blockIdx.x * LANES) + sl4
                       + (size_t)(h * 8) * HW4;
    const float4* xb4 = reinterpret_cast<const float4*>(x) + base4;

    // ---- Pass 1: stream 8 channels; 4 -> regs, 4 -> smem; accumulate ----
    float4 r[NREG];
    float s0a = 0.f, s1a = 0.f, s2a = 0.f, s3a = 0.f;

    #pragma unroll
    for (int cc = 0; cc < NREG; cc++) {
        r[cc] = __ldcs(xb4 + (size_t)cc * HW4);
        s0a += r[cc].x; s1a += r[cc].y; s2a += r[cc].z; s3a += r[cc].w;
    }
    #pragma unroll
    for (int cc = 0; cc < NSMEM; cc++) {
        float4 v = __ldcs(xb4 + (size_t)(NREG + cc) * HW4);
        sstage[cc * NTHR + t] = v;
        s0a += v.x; s1a += v.y; s2a += v.z; s3a += v.w;
    }
    reinterpret_cast<float4*>(sgrp)[h * LANES + sl4] =
        make_float4(s0a, s1a, s2a, s3a);
    __syncthreads();

    // ---- Gate computation: one thread per spatial location ----
    if (t < TILE_S) {
        float S8[8];
        #pragma unroll
        for (int j = 0; j < 8; j++)
            S8[j] = (sgrp[(4*j)   * TILE_S + t] + sgrp[(4*j+1) * TILE_S + t])
                  + (sgrp[(4*j+2) * TILE_S + t] + sgrp[(4*j+3) * TILE_S + t]);

        float S4[4], S2[2], S1;
        #pragma unroll
        for (int j = 0; j < 4; j++) S4[j] = S8[2*j] + S8[2*j+1];
        S2[0] = S4[0] + S4[1];
        S2[1] = S4[2] + S4[3];
        S1    = S2[0] + S2[1];

        // feats in reference concat order: [scale1, scale2, scale4, scale8]
        float f[15];
        f[0] = S1 * (1.0f / 256.0f);
        f[1] = S2[0] * (1.0f / 128.0f);
        f[2] = S2[1] * (1.0f / 128.0f);
        #pragma unroll
        for (int j = 0; j < 4; j++) f[3 + j] = S4[j] * (1.0f / 64.0f);
        #pragma unroll
        for (int j = 0; j < 8; j++) f[7 + j] = S8[j] * (1.0f / 32.0f);

        float mu = 0.0f;
        #pragma unroll
        for (int j = 0; j < 15; j++) mu += f[j];
        mu *= (1.0f / 15.0f);

        float var = 0.0f;
        #pragma unroll
        for (int j = 0; j < 15; j++) {
            float d = f[j] - mu;
            var += d * d;
        }
        var *= (1.0f / 15.0f);
        const float inv_std = rsqrtf(var);

        const float* wr = weight + (size_t)(s0 + t) * 15;
        float z = 0.0f;
        #pragma unroll
        for (int j = 0; j < 15; j++)
            z += (f[j] - mu) * __ldg(wr + j);
        z *= inv_std;

        sgate[t] = 1.0f / (1.0f + expf(-z));
    }
    __syncthreads();

    // ---- Pass 2: multiply staged data by gate, streaming stores ----
    const float4 gate4 = reinterpret_cast<const float4*>(sgate)[sl4];
    float4* ob4 = reinterpret_cast<float4*>(out) + base4;

    #pragma unroll
    for (int cc = 0; cc < NREG; cc++) {
        float4 v = r[cc];
        v.x *= gate4.x; v.y *= gate4.y; v.z *= gate4.z; v.w *= gate4.w;
        __stcs(ob4 + (size_t)cc * HW4, v);
    }
    #pragma unroll
    for (int cc = 0; cc < NSMEM; cc++) {
        float4 v = sstage[cc * NTHR + t];
        v.x *= gate4.x; v.y *= gate4.y; v.z *= gate4.z; v.w *= gate4.w;
        __stcs(ob4 + (size_t)(NREG + cc) * HW4, v);
    }
}

extern "C" void kernel_launch(void* const* d_in, const int* in_sizes, int n_in,
                              void* d_out, int out_size)
{
    const float* x      = (const float*)d_in[0];
    const float* weight = (const float*)d_in[1];
    float* out          = (float*)d_out;

    dim3 grid(HW / TILE_S, BATCH);   // (49, 64)
    ppca_gate_kernel<<<grid, NTHR>>>(x, weight, out);
}